// round 4
// baseline (speedup 1.0000x reference)
#include <cuda_runtime.h>
#include <cuda_bf16.h>
#include <float.h>

// Problem constants (fixed by setup_inputs)
#define BB   32
#define DD   256
#define HW   1024          // H*W = 32*32
#define NN   (BB*HW)       // 32768 vectors
#define KK   1024          // codebook size

#define ZQ_SIZE  (NN*DD)   // 8388608
#define IDX_OFF  ZQ_SIZE
#define LOSS_OFF (ZQ_SIZE + NN)

// GEMM tiling
#define TN 64     // rows (n) per block
#define TK 128    // cols (k) per k-tile
#define DC 64     // depth chunk for B tile
#define BS_PAD 132

// ---------------- scratch (no allocations allowed) ----------------
__device__ float g_cbnorm[KK];
__device__ float g_znorm[NN];
__device__ int   g_idx[NN];
__device__ float g_partial[256];

// ---------------- kernel 1a: codebook squared norms ----------------
// Replicates XLA fp32 scalar reduce: acc = RN(acc + RN(v*v)), d ascending.
__global__ void cbnorm_kernel(const float* __restrict__ cb) {
    int k = blockIdx.x * blockDim.x + threadIdx.x;
    if (k >= KK) return;
    const float* row = cb + k * DD;
    float acc = 0.f;
    for (int d = 0; d < DD; d++) {
        float v = row[d];
        acc = __fadd_rn(acc, __fmul_rn(v, v));
    }
    g_cbnorm[k] = acc;
}

// ---------------- kernel 1b: z squared norms (per flattened row) ----------------
// Row n = b*1024 + hw; element d lives at z[(b*256 + d)*1024 + hw].
// Strictly sequential d=0..255, separate mul/add, matching the reference's
// fp32 reduce order. Loads are coalesced across threads (consecutive hw).
__global__ void znorm_kernel(const float* __restrict__ z) {
    int n = blockIdx.x * blockDim.x + threadIdx.x;
    if (n >= NN) return;
    int b  = n >> 10;
    int hw = n & 1023;
    const float* p = z + ((size_t)b << 18) + hw;   // b*256*1024 + hw
    float acc = 0.f;
    #pragma unroll 8
    for (int d = 0; d < DD; d++) {
        float v = p[(size_t)d << 10];
        acc = __fadd_rn(acc, __fmul_rn(v, v));
    }
    g_znorm[n] = acc;
}

// ---------------- kernel 2: fused GEMM + argmin ----------------
// Reference numerics: d = RN( RN(znorm_n + cbnorm_k) - 2*dot ).
// The (znorm + cbnorm) add quantizes distances to ulp(~256) ~ 1.5e-5; ties at
// that quantum are broken by lowest k (jnp.argmin first-occurrence).
__global__ void __launch_bounds__(256, 2)
gemm_argmin_kernel(const float* __restrict__ z, const float* __restrict__ cb) {
    extern __shared__ float smem[];
    float (*As)[TN]     = (float(*)[TN])smem;                 // [256][64]  64 KB
    float (*Bs)[BS_PAD] = (float(*)[BS_PAD])(smem + DD * TN); // [64][132]

    const int t  = threadIdx.x;
    const int n0 = blockIdx.x * TN;
    const int b  = n0 >> 10;          // HW = 1024 per batch image
    const int hw = n0 & 1023;

    // Load full A tile: 64 rows x 256 depth. Coalesced over hw.
    for (int i = t; i < TN * DD; i += 256) {
        int d = i >> 6;               // /64
        int n = i & 63;
        As[d][n] = z[((b << 8) + d) * HW + hw + n];
    }

    const int tx = t & 31;            // k dimension: 32 groups of 4
    const int ty = t >> 5;            // n dimension: 8 groups of 8 (== warp id)

    // Per-row ||z||^2 (same value reference adds before the final subtract)
    float zn[8];
    #pragma unroll
    for (int i = 0; i < 8; i++) zn[i] = g_znorm[n0 + ty * 8 + i];

    float bestd[8];
    int   bestk[8];
    #pragma unroll
    for (int i = 0; i < 8; i++) { bestd[i] = FLT_MAX; bestk[i] = 0; }

    for (int k0 = 0; k0 < KK; k0 += TK) {
        float acc[8][4];
        #pragma unroll
        for (int i = 0; i < 8; i++)
            #pragma unroll
            for (int j = 0; j < 4; j++) acc[i][j] = 0.f;

        for (int d0 = 0; d0 < DD; d0 += DC) {
            __syncthreads();  // previous Bs reads done (also covers As readiness)
            for (int i = t; i < TK * DC; i += 256) {
                int dd = i & 63;
                int kk = i >> 6;
                Bs[dd][kk] = cb[(k0 + kk) * DD + d0 + dd];
            }
            __syncthreads();

            #pragma unroll 8
            for (int d = 0; d < DC; d++) {
                float4 a0 = *(const float4*)&As[d0 + d][ty * 8];
                float4 a1 = *(const float4*)&As[d0 + d][ty * 8 + 4];
                float4 bv = *(const float4*)&Bs[d][tx * 4];
                float a[8] = {a0.x, a0.y, a0.z, a0.w, a1.x, a1.y, a1.z, a1.w};
                float bb[4] = {bv.x, bv.y, bv.z, bv.w};
                #pragma unroll
                for (int i = 0; i < 8; i++)
                    #pragma unroll
                    for (int j = 0; j < 4; j++)
                        acc[i][j] = fmaf(a[i], bb[j], acc[i][j]);
            }
        }

        // epilogue: reference-rounded distance, running argmin
        float cn[4];
        #pragma unroll
        for (int j = 0; j < 4; j++) cn[j] = g_cbnorm[k0 + tx * 4 + j];
        #pragma unroll
        for (int i = 0; i < 8; i++) {
            #pragma unroll
            for (int j = 0; j < 4; j++) {
                float s    = __fadd_rn(zn[i], cn[j]);          // RN(znorm + cbnorm)
                float dist = __fadd_rn(s, -2.0f * acc[i][j]);  // RN(s - 2*dot), 2*dot exact
                int   k    = k0 + tx * 4 + j;
                if (dist < bestd[i]) { bestd[i] = dist; bestk[i] = k; }
            }
        }
    }

    // Warp-level argmin across lanes (lowest-index tiebreak)
    #pragma unroll
    for (int i = 0; i < 8; i++) {
        float d = bestd[i];
        int   k = bestk[i];
        #pragma unroll
        for (int off = 16; off; off >>= 1) {
            float d2 = __shfl_xor_sync(0xFFFFFFFFu, d, off);
            int   k2 = __shfl_xor_sync(0xFFFFFFFFu, k, off);
            if (d2 < d || (d2 == d && k2 < k)) { d = d2; k = k2; }
        }
        if (tx == 0) g_idx[n0 + ty * 8 + i] = k;
    }
}

// ---------------- kernel 3: gather + write zq_st (transposed) + indices + loss ----
#define GN 128    // n per block
__global__ void gather_kernel(const float* __restrict__ z,
                              const float* __restrict__ cb,
                              float* __restrict__ out,
                              int write_extra) {
    __shared__ int   sidx[GN];
    __shared__ float tile[32][129];
    __shared__ float red[8];

    const int t   = threadIdx.x;
    const int n0  = blockIdx.x * GN;
    const int b   = n0 >> 10;
    const int hw0 = n0 & 1023;

    if (t < GN) sidx[t] = g_idx[n0 + t];

    const int w = t >> 5, l = t & 31;
    float lsum = 0.f;

    for (int d0 = 0; d0 < DD; d0 += 32) {
        __syncthreads();   // sidx ready (1st iter) / tile reads done (later iters)
        for (int nn = w; nn < GN; nn += 8) {
            tile[l][nn] = cb[sidx[nn] * DD + d0 + l];
        }
        __syncthreads();
        for (int i = t; i < 32 * GN; i += 256) {
            int dd = i >> 7;          // /128
            int n  = i & 127;
            int d  = d0 + dd;
            float q  = tile[dd][n];
            int   zi = ((b << 8) + d) * HW + hw0 + n;
            float zv = z[zi];
            float df = __fsub_rn(q, zv);
            // straight-through output replicated bitwise: zp + RN(zq - zp)
            out[zi] = __fadd_rn(zv, df);
            lsum = fmaf(df, df, lsum);    // loss uses (zq - zp)^2
        }
    }

    // deterministic block reduction
    #pragma unroll
    for (int off = 16; off; off >>= 1)
        lsum += __shfl_xor_sync(0xFFFFFFFFu, lsum, off);
    if (l == 0) red[w] = lsum;
    __syncthreads();
    if (t == 0) {
        float s = 0.f;
        #pragma unroll
        for (int i = 0; i < 8; i++) s += red[i];
        g_partial[blockIdx.x] = s;
    }

    if (write_extra && t < GN)
        out[IDX_OFF + n0 + t] = (float)sidx[t];
}

// ---------------- kernel 4: finalize loss ----------------
__global__ void loss_kernel(float* __restrict__ out) {
    __shared__ float red[8];
    int t = threadIdx.x;
    float s = g_partial[t];           // 256 partials, 256 threads
    #pragma unroll
    for (int off = 16; off; off >>= 1)
        s += __shfl_xor_sync(0xFFFFFFFFu, s, off);
    if ((t & 31) == 0) red[t >> 5] = s;
    __syncthreads();
    if (t == 0) {
        double tot = 0.0;
        #pragma unroll
        for (int i = 0; i < 8; i++) tot += (double)red[i];
        // vq_loss + commitment (numerically identical) = 2 * mean((zq - z)^2)
        out[LOSS_OFF] = (float)(2.0 * tot / (double)ZQ_SIZE);
    }
}

// ---------------- launch ----------------
extern "C" void kernel_launch(void* const* d_in, const int* in_sizes, int n_in,
                              void* d_out, int out_size) {
    const float* z  = (const float*)d_in[0];
    const float* cb = (const float*)d_in[1];
    float* out = (float*)d_out;

    int write_extra = (out_size >= LOSS_OFF + 1) ? 1 : 0;

    cbnorm_kernel<<<KK / 256, 256>>>(cb);
    znorm_kernel<<<NN / 256, 256>>>(z);

    size_t smem = (size_t)DD * TN * sizeof(float) + (size_t)DC * BS_PAD * sizeof(float);
    cudaFuncSetAttribute(gemm_argmin_kernel,
                         cudaFuncAttributeMaxDynamicSharedMemorySize, (int)smem);
    gemm_argmin_kernel<<<NN / TN, 256, smem>>>(z, cb);

    gather_kernel<<<NN / GN, 256>>>(z, cb, out, write_extra);

    if (write_extra)
        loss_kernel<<<1, 256>>>(out);
}

// round 5
// speedup vs baseline: 1.0968x; 1.0968x over previous
#include <cuda_runtime.h>
#include <cuda_bf16.h>
#include <float.h>

// Problem constants (fixed by setup_inputs)
#define BB   32
#define DD   256
#define HW   1024          // H*W = 32*32
#define NN   (BB*HW)       // 32768 vectors
#define KK   1024          // codebook size

#define ZQ_SIZE  (NN*DD)   // 8388608
#define IDX_OFF  ZQ_SIZE
#define LOSS_OFF (ZQ_SIZE + NN)

// GEMM tiling
#define TN 64     // rows (n) per block
#define TK 128    // cols (k) per k-tile
#define DC 64     // depth chunk for B tile
#define BS_PAD 132

typedef unsigned long long u64;

// packed dual fp32 FMA: each 32-bit half is an independent IEEE RN fma —
// bit-identical per lane to scalar fmaf, 2x the fma-pipe throughput.
__device__ __forceinline__ void ffma2(u64& acc, u64 a, u64 b) {
    asm("fma.rn.f32x2 %0, %1, %2, %3;" : "=l"(acc) : "l"(a), "l"(b), "l"(acc));
}
__device__ __forceinline__ u64 bcast2(float x) {
    u64 r; asm("mov.b64 %0, {%1, %1};" : "=l"(r) : "f"(x)); return r;
}
__device__ __forceinline__ void unpack2(u64 v, float& lo, float& hi) {
    asm("mov.b64 {%0, %1}, %2;" : "=f"(lo), "=f"(hi) : "l"(v));
}

// ---------------- scratch (no allocations allowed) ----------------
__device__ float g_cbnorm[KK];
__device__ float g_znorm[NN];
__device__ int   g_idx[NN];
__device__ float g_partial[2048];

// ---------------- kernel 1a: codebook squared norms ----------------
// Replicates XLA fp32 scalar reduce: acc = RN(acc + RN(v*v)), d ascending.
__global__ void cbnorm_kernel(const float* __restrict__ cb) {
    int k = blockIdx.x * blockDim.x + threadIdx.x;
    if (k >= KK) return;
    const float* row = cb + k * DD;
    float acc = 0.f;
    for (int d = 0; d < DD; d++) {
        float v = row[d];
        acc = __fadd_rn(acc, __fmul_rn(v, v));
    }
    g_cbnorm[k] = acc;
}

// ---------------- kernel 1b: z squared norms (per flattened row) ----------------
// Strictly sequential d=0..255, separate mul/add — matches reference rounding.
__global__ void znorm_kernel(const float* __restrict__ z) {
    int n = blockIdx.x * blockDim.x + threadIdx.x;
    if (n >= NN) return;
    int b  = n >> 10;
    int hw = n & 1023;
    const float* p = z + ((size_t)b << 18) + hw;   // b*256*1024 + hw
    float acc = 0.f;
    #pragma unroll 8
    for (int d = 0; d < DD; d++) {
        float v = p[(size_t)d << 10];
        acc = __fadd_rn(acc, __fmul_rn(v, v));
    }
    g_znorm[n] = acc;
}

// ---------------- kernel 2: fused GEMM + argmin (FFMA2 packed fp32) ----------------
// dist = RN( RN(znorm_n + cbnorm_k) - 2*dot ); accumulation order identical to
// the proven scalar version (d ascending in DC chunks); rows paired 2-wide in
// f32x2 so each half is the exact same fp32 FMA sequence as before.
__global__ void __launch_bounds__(256, 2)
gemm_argmin_kernel(const float* __restrict__ z, const float* __restrict__ cb) {
    extern __shared__ float smem[];
    float (*As)[TN]     = (float(*)[TN])smem;                 // [256][64]  64 KB
    float (*Bs)[BS_PAD] = (float(*)[BS_PAD])(smem + DD * TN); // [64][132]

    const int t  = threadIdx.x;
    const int n0 = blockIdx.x * TN;
    const int b  = n0 >> 10;          // HW = 1024 per batch image
    const int hw = n0 & 1023;

    // Load full A tile: 64 rows x 256 depth. Coalesced over hw.
    for (int i = t; i < TN * DD; i += 256) {
        int d = i >> 6;               // /64
        int n = i & 63;
        As[d][n] = z[((b << 8) + d) * HW + hw + n];
    }

    const int tx = t & 31;            // k dimension: 32 groups of 4
    const int ty = t >> 5;            // n dimension: 8 groups of 8 (== warp id)

    // Per-row ||z||^2
    float zn[8];
    #pragma unroll
    for (int i = 0; i < 8; i++) zn[i] = g_znorm[n0 + ty * 8 + i];

    float bestd[8];
    int   bestk[8];
    #pragma unroll
    for (int i = 0; i < 8; i++) { bestd[i] = FLT_MAX; bestk[i] = 0; }

    for (int k0 = 0; k0 < KK; k0 += TK) {
        // accP[j][p]: col j (0..3), row-pair p (rows 2p, 2p+1 in low/high halves)
        u64 accP[4][4];
        #pragma unroll
        for (int j = 0; j < 4; j++)
            #pragma unroll
            for (int p = 0; p < 4; p++) accP[j][p] = 0ull;

        for (int d0 = 0; d0 < DD; d0 += DC) {
            __syncthreads();  // previous Bs reads done (also covers As readiness)
            for (int i = t; i < TK * DC; i += 256) {
                int dd = i & 63;
                int kk = i >> 6;
                Bs[dd][kk] = cb[(k0 + kk) * DD + d0 + dd];
            }
            __syncthreads();

            #pragma unroll 4
            for (int d = 0; d < DC; d++) {
                // A row pairs straight from smem as 64-bit packs (32B aligned)
                ulonglong2 aP01 = *(const ulonglong2*)&As[d0 + d][ty * 8];
                ulonglong2 aP23 = *(const ulonglong2*)&As[d0 + d][ty * 8 + 4];
                u64 ap[4] = {aP01.x, aP01.y, aP23.x, aP23.y};
                float4 bv = *(const float4*)&Bs[d][tx * 4];
                u64 bp[4] = {bcast2(bv.x), bcast2(bv.y), bcast2(bv.z), bcast2(bv.w)};
                #pragma unroll
                for (int j = 0; j < 4; j++)
                    #pragma unroll
                    for (int p = 0; p < 4; p++)
                        ffma2(accP[j][p], ap[p], bp[j]);
            }
        }

        // epilogue: reference-rounded distance, running argmin
        float cn[4];
        #pragma unroll
        for (int j = 0; j < 4; j++) cn[j] = g_cbnorm[k0 + tx * 4 + j];
        #pragma unroll
        for (int p = 0; p < 4; p++) {
            #pragma unroll
            for (int j = 0; j < 4; j++) {
                float alo, ahi;
                unpack2(accP[j][p], alo, ahi);
                int k = k0 + tx * 4 + j;
                {
                    int   i    = 2 * p;
                    float s    = __fadd_rn(zn[i], cn[j]);
                    float dist = __fadd_rn(s, -2.0f * alo);
                    if (dist < bestd[i]) { bestd[i] = dist; bestk[i] = k; }
                }
                {
                    int   i    = 2 * p + 1;
                    float s    = __fadd_rn(zn[i], cn[j]);
                    float dist = __fadd_rn(s, -2.0f * ahi);
                    if (dist < bestd[i]) { bestd[i] = dist; bestk[i] = k; }
                }
            }
        }
    }

    // Warp-level argmin across lanes (lowest-index tiebreak)
    #pragma unroll
    for (int i = 0; i < 8; i++) {
        float d = bestd[i];
        int   k = bestk[i];
        #pragma unroll
        for (int off = 16; off; off >>= 1) {
            float d2 = __shfl_xor_sync(0xFFFFFFFFu, d, off);
            int   k2 = __shfl_xor_sync(0xFFFFFFFFu, k, off);
            if (d2 < d || (d2 == d && k2 < k)) { d = d2; k = k2; }
        }
        if (tx == 0) g_idx[n0 + ty * 8 + i] = k;
    }
}

// ---------------- kernel 3: gather + write zq_st + indices + loss partials ----
// 2D grid: x = n-tile (128 rows), y = d-chunk (32 depths). 2048 independent
// blocks, 2 barriers each — removes the serial d-loop that starved the old one.
#define GN 128
#define GD 32
__global__ void gather_kernel(const float* __restrict__ z,
                              const float* __restrict__ cb,
                              float* __restrict__ out,
                              int write_extra) {
    __shared__ int   sidx[GN];
    __shared__ float tile[GD][GN + 1];   // pad -> gather writes conflict-free
    __shared__ float red[8];

    const int t   = threadIdx.x;
    const int n0  = blockIdx.x * GN;
    const int d0  = blockIdx.y * GD;
    const int b   = n0 >> 10;
    const int hw0 = n0 & 1023;

    if (t < GN) sidx[t] = g_idx[n0 + t];
    __syncthreads();

    const int w = t >> 5, l = t & 31;

    // gather: warp per n, lanes over 32 consecutive d -> coalesced 128B reads
    for (int nn = w; nn < GN; nn += 8)
        tile[l][nn] = cb[sidx[nn] * DD + d0 + l];
    __syncthreads();

    float lsum = 0.f;
    #pragma unroll
    for (int r = 0; r < (GD * GN) / 256; r++) {   // 16 iterations
        int i  = r * 256 + t;
        int dd = i >> 7;          // /128
        int n  = i & 127;
        int d  = d0 + dd;
        float q  = tile[dd][n];
        int   zi = ((b << 8) + d) * HW + hw0 + n;
        float zv = z[zi];
        float df = __fsub_rn(q, zv);
        out[zi] = __fadd_rn(zv, df);       // zq_st = zp + RN(zq - zp), bitwise
        lsum = fmaf(df, df, lsum);
    }

    // deterministic block reduction
    #pragma unroll
    for (int off = 16; off; off >>= 1)
        lsum += __shfl_xor_sync(0xFFFFFFFFu, lsum, off);
    if (l == 0) red[w] = lsum;
    __syncthreads();
    if (t == 0) {
        float s = 0.f;
        #pragma unroll
        for (int i = 0; i < 8; i++) s += red[i];
        g_partial[blockIdx.y * gridDim.x + blockIdx.x] = s;
    }

    if (write_extra && blockIdx.y == 0 && t < GN)
        out[IDX_OFF + n0 + t] = (float)sidx[t];
}

// ---------------- kernel 4: finalize loss ----------------
__global__ void loss_kernel(float* __restrict__ out) {
    __shared__ float red[8];
    int t = threadIdx.x;
    float s = 0.f;
    #pragma unroll
    for (int i = 0; i < 8; i++)           // 2048 partials, fixed order
        s += g_partial[t * 8 + i];
    #pragma unroll
    for (int off = 16; off; off >>= 1)
        s += __shfl_xor_sync(0xFFFFFFFFu, s, off);
    if ((t & 31) == 0) red[t >> 5] = s;
    __syncthreads();
    if (t == 0) {
        double tot = 0.0;
        #pragma unroll
        for (int i = 0; i < 8; i++) tot += (double)red[i];
        // vq_loss + commitment (numerically identical) = 2 * mean((zq - z)^2)
        out[LOSS_OFF] = (float)(2.0 * tot / (double)ZQ_SIZE);
    }
}

// ---------------- launch ----------------
extern "C" void kernel_launch(void* const* d_in, const int* in_sizes, int n_in,
                              void* d_out, int out_size) {
    const float* z  = (const float*)d_in[0];
    const float* cb = (const float*)d_in[1];
    float* out = (float*)d_out;

    int write_extra = (out_size >= LOSS_OFF + 1) ? 1 : 0;

    cbnorm_kernel<<<KK / 128, 128>>>(cb);
    znorm_kernel<<<NN / 256, 256>>>(z);

    size_t smem = (size_t)DD * TN * sizeof(float) + (size_t)DC * BS_PAD * sizeof(float);
    cudaFuncSetAttribute(gemm_argmin_kernel,
                         cudaFuncAttributeMaxDynamicSharedMemorySize, (int)smem);
    gemm_argmin_kernel<<<NN / TN, 256, smem>>>(z, cb);

    gather_kernel<<<dim3(NN / GN, DD / GD), 256>>>(z, cb, out, write_extra);

    if (write_extra)
        loss_kernel<<<1, 256>>>(out);
}